// round 16
// baseline (speedup 1.0000x reference)
#include <cuda_runtime.h>
#include <cuda_bf16.h>
#include <math.h>

#define Bb    64
#define Tt    20
#define TMX   19
#define Pp    36
#define Vv    32000
#define Ee    300
#define Hh    512
#define Dd    512
#define Gg    2048          // 4*H
#define KL    1324          // E + D + H
#define KPK   1344          // KL padded to 8*168
#define KSPL  168           // per-split K
#define NROW  1216          // B * TMX
#define NBLK1 500           // Vv/64
#define KP    304           // Ee padded to multiple of 16
#define MPAD  1280          // NROW padded to multiple of 128

#define OFF1  ((size_t)Bb*TMX*Vv)
#define OFF2  (OFF1 + (size_t)Bb*TMX*Pp)
#define OFF3  (OFF2 + (size_t)Bb*TMX)
#define OFF4  (OFF3 + (size_t)Bb)

// ---------------- scratch (zero-initialized device globals) ----------------
__device__ int      g_sort[Bb];
__device__ int      g_dec[Bb];
__device__ float    g_epart[NBLK1*Ee];
__device__ float    g_wlin[Vv];
__device__ float    g_sumWH[Hh];
__device__ float    g_sumWRp[Dd];
__device__ float    g_sumwlin;
__device__ float    g_q[Bb*Ee];
__device__ float    g_swrb[Bb];
__device__ float    g_rlin[Bb*Pp];
__device__ float    g_wrsumV[Bb*Pp];
__device__ float    g_props[Bb*Pp*Dd];
__device__ float    g_RH[Bb*Pp*Hh];
__device__ float    g_c[Bb*Hh];
__device__ float    g_Ssum[Bb*Dd];
__device__ float    g_xh[Bb*KPK];       // [emb(300) | fb(512) | h(512) | pad0(20)]
__device__ unsigned g_Whi[Gg*KPK];      // tf32 hi of packed [W_ih | W_hh], pad 0
__device__ unsigned g_Wlo[Gg*KPK];      // tf32 lo
__device__ float    g_bias[Gg];         // b_ih + b_hh
__device__ float    g_gpart[8*Bb*Gg];
__device__ float    g_Hseq[NROW*Hh];
__device__ float    g_X[MPAD*KP];       // padded; pad region stays 0 forever
__device__ float    g_rowoff[NROW];
__device__ float    g_maskf[NROW];

__device__ __forceinline__ float fsig(float x) { return 1.0f / (1.0f + __expf(-x)); }
__device__ __forceinline__ float ftanh(float x) {
    float e = __expf(-2.0f * fabsf(x));
    float r = (1.0f - e) / (1.0f + e);
    return copysignf(r, x);
}
__device__ __forceinline__ float wred(float v) {
    #pragma unroll
    for (int o = 16; o; o >>= 1) v += __shfl_xor_sync(0xffffffffu, v, o);
    return v;
}
__device__ __forceinline__ float wmax(float v) {
    #pragma unroll
    for (int o = 16; o; o >>= 1) v = fmaxf(v, __shfl_xor_sync(0xffffffffu, v, o));
    return v;
}
__device__ __forceinline__ unsigned cvt_tf32(float x) {
    unsigned u;
    asm("cvt.rna.tf32.f32 %0, %1;" : "=r"(u) : "f"(x));
    return u;
}
__device__ __forceinline__ void mma_tf32(float* d, const unsigned* a, const unsigned* b) {
    asm volatile(
        "mma.sync.aligned.m16n8k8.row.col.f32.tf32.tf32.f32 "
        "{%0,%1,%2,%3}, {%4,%5,%6,%7}, {%8,%9}, {%0,%1,%2,%3};"
        : "+f"(d[0]), "+f"(d[1]), "+f"(d[2]), "+f"(d[3])
        : "r"(a[0]), "r"(a[1]), "r"(a[2]), "r"(a[3]), "r"(b[0]), "r"(b[1]));
}

// ---- K0: stable argsort(-lengths) ----
__global__ void k0_setup(const int* __restrict__ clen) {
    __shared__ int len[Bb];
    int t = threadIdx.x;
    if (t < Bb) len[t] = clen[t];
    __syncthreads();
    if (t < Bb) {
        int li = len[t], pos = 0;
        for (int j = 0; j < Bb; j++) {
            int lj = len[j];
            if (lj > li || (lj == li && j < t)) pos++;
        }
        g_sort[pos] = t;
        g_dec[pos]  = li - 1;
    }
}

// ---- KW: pack LSTM weights to tf32 hi/lo, combine biases ----
__global__ void __launch_bounds__(256) kw_prep(const float* __restrict__ Wih,
                                               const float* __restrict__ Whh,
                                               const float* __restrict__ bih,
                                               const float* __restrict__ bhh) {
    int n = blockIdx.x;
    for (int k = threadIdx.x; k < KL; k += 256) {
        float v = (k < Ee + Dd) ? Wih[(size_t)n * (Ee + Dd) + k]
                                : Whh[(size_t)n * Hh + (k - Ee - Dd)];
        unsigned hi = cvt_tf32(v);
        g_Whi[(size_t)n * KPK + k] = hi;
        g_Wlo[(size_t)n * KPK + k] = cvt_tf32(v - __uint_as_float(hi));
    }
    if (threadIdx.x == 0) g_bias[n] = bih[n] + bhh[n];
}

// ---- K1: vocab pass: w_lin + per-block partial column sums of emb_W ----
__global__ void __launch_bounds__(256) k1_vocab(const float* __restrict__ emb,
                                                const float* __restrict__ wW,
                                                const float* __restrict__ wb) {
    __shared__ float swarp[8][Ee];
    int tid = threadIdx.x, lane = tid & 31, w = tid >> 5;
    float wbv = wb[0];
    float seacc[10];
    #pragma unroll
    for (int j = 0; j < 10; j++) seacc[j] = 0.0f;
    #pragma unroll
    for (int r = 0; r < 8; r++) {
        int v = blockIdx.x * 64 + w * 8 + r;
        const float* row = emb + (size_t)v * Ee;
        float acc = 0.0f;
        #pragma unroll
        for (int j = 0; j < 10; j++) {
            int e = lane + 32 * j;
            if (e < Ee) {
                float x = row[e];
                acc += x * wW[e];
                seacc[j] += x;
            }
        }
        acc = wred(acc);
        if (lane == 0) g_wlin[v] = acc + wbv;
    }
    #pragma unroll
    for (int j = 0; j < 10; j++) {
        int e = lane + 32 * j;
        if (e < Ee) swarp[w][e] = seacc[j];
    }
    __syncthreads();
    for (int e = tid; e < Ee; e += 256) {
        float s = 0.0f;
        #pragma unroll
        for (int w2 = 0; w2 < 8; w2++) s += swarp[w2][e];
        g_epart[blockIdx.x * Ee + e] = s;
    }
}

// ---- K2: reduce partials -> sum_emb; derived sums ----
__global__ void k2_derived(const float* __restrict__ whW, const float* __restrict__ whb,
                           const float* __restrict__ wrW, const float* __restrict__ wrb,
                           const float* __restrict__ wW,  const float* __restrict__ wb) {
    __shared__ float se[Ee];
    int t = threadIdx.x;
    for (int e = t; e < Ee; e += 512) {
        float s0 = 0.0f, s1 = 0.0f, s2 = 0.0f, s3 = 0.0f;
        for (int blk = 0; blk < NBLK1; blk += 4) {
            s0 += g_epart[(blk + 0) * Ee + e];
            s1 += g_epart[(blk + 1) * Ee + e];
            s2 += g_epart[(blk + 2) * Ee + e];
            s3 += g_epart[(blk + 3) * Ee + e];
        }
        se[e] = (s0 + s1) + (s2 + s3);
    }
    __syncthreads();
    if (t < Hh) {
        const float* r1 = whW + t * Ee;
        const float* r2 = wrW + t * Ee;
        float a = 0.0f, b2 = 0.0f;
        for (int e = 0; e < Ee; e++) { a += r1[e] * se[e]; b2 += r2[e] * se[e]; }
        g_sumWH[t]  = a  + (float)Vv * whb[t];
        g_sumWRp[t] = b2 + (float)Vv * wrb[t];
    }
    if (t == 0) {
        float s = 0.0f;
        for (int e = 0; e < Ee; e++) s += wW[e] * se[e];
        g_sumwlin = s + (float)Vv * wb[0];
    }
}

// ---- K3: per-batch setup ----
__global__ void __launch_bounds__(1024) k3_batch(
        const float* __restrict__ h0, const float* __restrict__ props,
        const int* __restrict__ caps, const float* __restrict__ emb,
        const float* __restrict__ wrb,
        const float* __restrict__ rW,  const float* __restrict__ rb,
        float* __restrict__ out) {
    int b = blockIdx.x, tid = threadIdx.x, lane = tid & 31, w = tid >> 5;
    int sb = g_sort[b];
    const float* pb = props + (size_t)sb * Pp * Dd;
    float* gp = g_props + (size_t)b * Pp * Dd;
    __shared__ float sS[Dd];

    for (int i = tid; i < Pp * Dd / 4; i += 1024)
        ((float4*)gp)[i] = ((const float4*)pb)[i];
    if (tid < Dd) {
        float s = 0.0f;
        #pragma unroll
        for (int p = 0; p < Pp; p++) s += pb[p * Dd + tid];
        sS[tid] = s;
        g_Ssum[b * Dd + tid] = s;
    }
    __syncthreads();

    if (w == 0) {
        float a = 0.0f;
        for (int d = lane; d < Dd; d += 32) a += sS[d] * wrb[d];
        a = wred(a);
        if (lane == 0) g_swrb[b] = a;
    }
    for (int p = w; p < Pp; p += 32) {
        float a1 = 0.0f, a2 = 0.0f;
        const float* rowp = pb + p * Dd;
        for (int d = lane; d < Dd; d += 32) {
            float x = rowp[d];
            a1 += x * rW[d];
            a2 += x * g_sumWRp[d];
        }
        a1 = wred(a1); a2 = wred(a2);
        if (lane == 0) {
            g_rlin[b * Pp + p]   = a1 + rb[0];
            g_wrsumV[b * Pp + p] = a2;
        }
    }
    if (tid < Hh) {
        float v = h0[(size_t)sb * Hh + tid];
        g_c[b * Hh + tid] = v;
        g_xh[b * KPK + Ee + Dd + tid] = v;   // h
        g_xh[b * KPK + Ee + tid] = 0.0f;     // fb
    }
    int cap0 = caps[sb * Tt + 0];
    if (tid < Ee) g_xh[b * KPK + tid] = emb[(size_t)cap0 * Ee + tid];
    int dec = g_dec[b];
    if (tid < TMX) {
        g_maskf[b * TMX + tid] = (tid < dec) ? 1.0f : 0.0f;
        out[OFF2 + b * TMX + tid] = (float)caps[sb * Tt + 1 + tid];
    }
    if (tid == 0) {
        out[OFF3 + b] = (float)dec;
        out[OFF4 + b] = (float)sb;
    }
}

// ---- K3Q: q = Ssum(64x512) @ wr_W(512x300) ----
__global__ void __launch_bounds__(256) k3q(const float* __restrict__ wrW) {
    __shared__ float As[16][64];
    __shared__ float Bs[16][64];
    int n0 = blockIdx.x * 64;
    int tid = threadIdx.x, tx = tid & 15, ty = tid >> 4;
    float acc[4][4] = {};
    for (int k0 = 0; k0 < Dd; k0 += 16) {
        #pragma unroll
        for (int i = 0; i < 4; i++) {
            int idx = tid + i * 256;
            int kk = idx & 15, mm = idx >> 4;
            As[kk][mm] = g_Ssum[mm * Dd + k0 + kk];
            int nn = idx & 63, kk2 = idx >> 6;
            Bs[kk2][nn] = (n0 + nn < Ee) ? wrW[(size_t)(k0 + kk2) * Ee + n0 + nn] : 0.0f;
        }
        __syncthreads();
        #pragma unroll
        for (int kk = 0; kk < 16; kk++) {
            float4 a  = *(const float4*)&As[kk][ty * 4];
            float4 bq = *(const float4*)&Bs[kk][tx * 4];
            float av[4] = {a.x, a.y, a.z, a.w};
            float bv[4] = {bq.x, bq.y, bq.z, bq.w};
            #pragma unroll
            for (int i = 0; i < 4; i++)
                #pragma unroll
                for (int j = 0; j < 4; j++) acc[i][j] += av[i] * bv[j];
        }
        __syncthreads();
    }
    #pragma unroll
    for (int i = 0; i < 4; i++)
        #pragma unroll
        for (int j = 0; j < 4; j++) {
            int n = n0 + tx * 4 + j;
            if (n < Ee) g_q[(ty * 4 + i) * Ee + n] = acc[i][j];
        }
}

// ---- K4: RH = props_s @ rh_W^T + rh_b ----
__global__ void __launch_bounds__(256) k4_rh(const float* __restrict__ rhW,
                                             const float* __restrict__ rhb) {
    __shared__ float As[16][64];
    __shared__ float Bs[16][64];
    int m0 = blockIdx.y * 64, n0 = blockIdx.x * 64;
    int tid = threadIdx.x, tx = tid & 15, ty = tid >> 4;
    float acc[4][4] = {};
    for (int k0 = 0; k0 < Dd; k0 += 16) {
        #pragma unroll
        for (int i = 0; i < 4; i++) {
            int idx = tid + i * 256;
            int kk = idx & 15, mm = idx >> 4;
            As[kk][mm] = g_props[(size_t)(m0 + mm) * Dd + k0 + kk];
            Bs[kk][mm] = rhW[(size_t)(n0 + mm) * Dd + k0 + kk];
        }
        __syncthreads();
        #pragma unroll
        for (int kk = 0; kk < 16; kk++) {
            float4 a  = *(const float4*)&As[kk][ty * 4];
            float4 bq = *(const float4*)&Bs[kk][tx * 4];
            float av[4] = {a.x, a.y, a.z, a.w};
            float bv[4] = {bq.x, bq.y, bq.z, bq.w};
            #pragma unroll
            for (int i = 0; i < 4; i++)
                #pragma unroll
                for (int j = 0; j < 4; j++) acc[i][j] += av[i] * bv[j];
        }
        __syncthreads();
    }
    #pragma unroll
    for (int i = 0; i < 4; i++)
        #pragma unroll
        for (int j = 0; j < 4; j++)
            g_RH[(size_t)(m0 + ty * 4 + i) * Hh + n0 + tx * 4 + j] = acc[i][j] + rhb[n0 + tx * 4 + j];
}

// ---- K5T: gates split-K via 2-term TF32 mma (fp32-accurate) ----
__global__ void __launch_bounds__(256) k5t() {
    __shared__ unsigned Ah[64 * 12], Al[64 * 12];
    __shared__ unsigned Bh[128 * 12], Bl[128 * 12];
    int n0 = blockIdx.x * 128;
    int ks = blockIdx.y * KSPL;
    int tid = threadIdx.x, lane = tid & 31, wid = tid >> 5;
    int wm = wid >> 2, wn = wid & 3;
    int gid = lane >> 2, ctg = lane & 3;

    float acc[2][4][4];
    #pragma unroll
    for (int mt = 0; mt < 2; mt++)
        #pragma unroll
        for (int nt = 0; nt < 4; nt++)
            #pragma unroll
            for (int r = 0; r < 4; r++) acc[mt][nt][r] = 0.0f;

    int brow = tid >> 1, bseg = (tid & 1) * 4;
    #pragma unroll 1
    for (int c = 0; c < KSPL / 8; c++) {
        int k0 = ks + c * 8;
        *(uint4*)&Bh[brow * 12 + bseg] = *(const uint4*)&g_Whi[(size_t)(n0 + brow) * KPK + k0 + bseg];
        *(uint4*)&Bl[brow * 12 + bseg] = *(const uint4*)&g_Wlo[(size_t)(n0 + brow) * KPK + k0 + bseg];
        if (tid < 128) {
            float4 av = *(const float4*)&g_xh[brow * KPK + k0 + bseg];
            uint4 h, l;
            h.x = cvt_tf32(av.x); l.x = cvt_tf32(av.x - __uint_as_float(h.x));
            h.y = cvt_tf32(av.y); l.y = cvt_tf32(av.y - __uint_as_float(h.y));
            h.z = cvt_tf32(av.z); l.z = cvt_tf32(av.z - __uint_as_float(h.z));
            h.w = cvt_tf32(av.w); l.w = cvt_tf32(av.w - __uint_as_float(h.w));
            *(uint4*)&Ah[brow * 12 + bseg] = h;
            *(uint4*)&Al[brow * 12 + bseg] = l;
        }
        __syncthreads();
        unsigned ah[2][4], al[2][4], bh[4][2], bl[4][2];
        #pragma unroll
        for (int mt = 0; mt < 2; mt++) {
            int mr = wm * 32 + mt * 16 + gid;
            ah[mt][0] = Ah[mr * 12 + ctg];       al[mt][0] = Al[mr * 12 + ctg];
            ah[mt][1] = Ah[(mr + 8) * 12 + ctg]; al[mt][1] = Al[(mr + 8) * 12 + ctg];
            ah[mt][2] = Ah[mr * 12 + ctg + 4];   al[mt][2] = Al[mr * 12 + ctg + 4];
            ah[mt][3] = Ah[(mr + 8) * 12 + ctg + 4]; al[mt][3] = Al[(mr + 8) * 12 + ctg + 4];
        }
        #pragma unroll
        for (int nt = 0; nt < 4; nt++) {
            int nr = wn * 32 + nt * 8 + gid;
            bh[nt][0] = Bh[nr * 12 + ctg];     bl[nt][0] = Bl[nr * 12 + ctg];
            bh[nt][1] = Bh[nr * 12 + ctg + 4]; bl[nt][1] = Bl[nr * 12 + ctg + 4];
        }
        #pragma unroll
        for (int mt = 0; mt < 2; mt++)
            #pragma unroll
            for (int nt = 0; nt < 4; nt++) {
                mma_tf32(acc[mt][nt], ah[mt], bh[nt]);
                mma_tf32(acc[mt][nt], ah[mt], bl[nt]);
                mma_tf32(acc[mt][nt], al[mt], bh[nt]);
            }
        __syncthreads();
    }
    float* pp = g_gpart + (size_t)blockIdx.y * Bb * Gg;
    #pragma unroll
    for (int mt = 0; mt < 2; mt++) {
        int mA = wm * 32 + mt * 16 + gid;
        int mB = mA + 8;
        #pragma unroll
        for (int nt = 0; nt < 4; nt++) {
            int v = n0 + wn * 32 + nt * 8 + 2 * ctg;
            *(float2*)&pp[mA * Gg + v] = make_float2(acc[mt][nt][0], acc[mt][nt][1]);
            *(float2*)&pp[mB * Gg + v] = make_float2(acc[mt][nt][2], acc[mt][nt][3]);
        }
    }
}

// ---- K6: per-step: LSTM pointwise + attention + state update ----
__global__ void __launch_bounds__(256) k6_step(int t, const int* __restrict__ caps,
                                               const float* __restrict__ emb,
                                               const float* __restrict__ whb,
                                               float* __restrict__ out) {
    int b = blockIdx.x, tid = threadIdx.x, lane = tid & 31, w = tid >> 5;
    __shared__ float sh[Hh], sr[Pp], satt[Pp], sred[16];
    __shared__ float s_hdot, s_hwb;

    float mask = g_maskf[b * TMX + t];
    float hdot_part = 0.0f, hwb_part = 0.0f;
    #pragma unroll
    for (int u = 0; u < 2; u++) {
        int h = tid + u * 256;
        float gi = g_bias[h];
        float gf = g_bias[512 + h];
        float gg = g_bias[1024 + h];
        float go = g_bias[1536 + h];
        #pragma unroll
        for (int s = 0; s < 8; s++) {
            const float* pp = g_gpart + (size_t)s * Bb * Gg + (size_t)b * Gg;
            gi += pp[h]; gf += pp[512 + h]; gg += pp[1024 + h]; go += pp[1536 + h];
        }
        float co = g_c[b * Hh + h];
        float cn = fsig(gf) * co + fsig(gi) * ftanh(gg);
        float hn = fsig(go) * ftanh(cn);
        sh[h] = hn;
        g_Hseq[(size_t)(b * TMX + t) * Hh + h] = hn;
        float hold = g_xh[b * KPK + Ee + Dd + h];
        g_c[b * Hh + h] = mask * cn + (1.0f - mask) * co;
        g_xh[b * KPK + Ee + Dd + h] = mask * hn + (1.0f - mask) * hold;
        hdot_part += hn * g_sumWH[h];
        hwb_part  += hn * whb[h];
    }
    hdot_part = wred(hdot_part);
    hwb_part  = wred(hwb_part);
    if (lane == 0) { sred[w] = hdot_part; sred[8 + w] = hwb_part; }
    __syncthreads();
    if (tid == 0) {
        float a = 0.0f, b2 = 0.0f;
        #pragma unroll
        for (int i = 0; i < 8; i++) { a += sred[i]; b2 += sred[8 + i]; }
        s_hdot = a; s_hwb = b2;
    }
    __syncthreads();

    for (int p = w; p < Pp; p += 8) {
        const float* rh = g_RH + (size_t)(b * Pp + p) * Hh;
        float a = 0.0f;
        for (int d = lane; d < Hh; d += 32) a += rh[d] * sh[d];
        a = wred(a);
        if (lane == 0) sr[p] = a + g_rlin[b * Pp + p];
    }
    __syncthreads();

    // warp 0: parallel softmax over 36 logits + rowoff
    if (w == 0) {
        float base = s_hdot + g_sumwlin;
        float r0v = (lane < Pp) ? sr[lane] : 0.0f;
        float r1v = (lane + 32 < Pp) ? sr[lane + 32] : 0.0f;
        float l0 = (lane < Pp) ? (base + g_wrsumV[b * Pp + lane] + r0v) : -1e30f;
        float l1 = (lane + 32 < Pp) ? (base + g_wrsumV[b * Pp + lane + 32] + r1v) : -1e30f;
        float mx = wmax(fmaxf(l0, l1));
        float e0 = (lane < Pp) ? __expf(l0 - mx) : 0.0f;
        float e1 = (lane + 32 < Pp) ? __expf(l1 - mx) : 0.0f;
        float den = wred(e0 + e1);
        float inv = 1.0f / den;
        if (lane < Pp) satt[lane] = e0 * inv;
        if (lane + 32 < Pp) satt[lane + 32] = e1 * inv;
        float rs = wred(r0v + r1v);
        if (lane == 0) g_rowoff[b * TMX + t] = rs + s_hwb + g_swrb[b];
    }
    __syncthreads();
    if (tid < Pp) out[OFF1 + (size_t)(b * TMX + t) * Pp + tid] = satt[tid] * mask;

    int capn = (t < TMX - 1) ? caps[g_sort[b] * Tt + t + 1] : 0;
    #pragma unroll
    for (int u = 0; u < 2; u++) {
        int d = tid + u * 256;
        float fbn = 0.0f;
        #pragma unroll 4
        for (int p = 0; p < Pp; p++) fbn += satt[p] * g_props[(size_t)(b * Pp + p) * Dd + d];
        float fold = g_xh[b * KPK + Ee + d];
        g_xh[b * KPK + Ee + d] = mask * fbn + (1.0f - mask) * fold;
    }
    // FIX: strided loop — Ee=300 > blockDim=256, the guard version left 44
    // stale embedding components per step (the 4.2e-2 failure).
    if (t < TMX - 1)
        for (int e = tid; e < Ee; e += 256)
            g_xh[b * KPK + e] = emb[(size_t)capn * Ee + e];
}

// ---- K7: X = Hseq @ wh_W + q  (writes into KP-padded g_X) ----
__global__ void __launch_bounds__(256) k7_x(const float* __restrict__ whW) {
    __shared__ float As[16][64];
    __shared__ float Bs[16][64];
    int m0 = blockIdx.y * 64, n0 = blockIdx.x * 64;
    int tid = threadIdx.x, tx = tid & 15, ty = tid >> 4;
    float acc[4][4] = {};
    for (int k0 = 0; k0 < Hh; k0 += 16) {
        #pragma unroll
        for (int i = 0; i < 4; i++) {
            int idxa = tid + i * 256;
            int kk = idxa & 15, mm = idxa >> 4;
            As[kk][mm] = g_Hseq[(size_t)(m0 + mm) * Hh + k0 + kk];
            int nn = idxa & 63, kk2 = idxa >> 6;
            Bs[kk2][nn] = (n0 + nn < Ee) ? whW[(size_t)(k0 + kk2) * Ee + n0 + nn] : 0.0f;
        }
        __syncthreads();
        #pragma unroll
        for (int kk = 0; kk < 16; kk++) {
            float4 a  = *(const float4*)&As[kk][ty * 4];
            float4 bq = *(const float4*)&Bs[kk][tx * 4];
            float av[4] = {a.x, a.y, a.z, a.w};
            float bv[4] = {bq.x, bq.y, bq.z, bq.w};
            #pragma unroll
            for (int i = 0; i < 4; i++)
                #pragma unroll
                for (int j = 0; j < 4; j++) acc[i][j] += av[i] * bv[j];
        }
        __syncthreads();
    }
    #pragma unroll
    for (int i = 0; i < 4; i++) {
        int m = m0 + ty * 4 + i;
        int bq = m / TMX;
        #pragma unroll
        for (int j = 0; j < 4; j++) {
            int n = n0 + tx * 4 + j;
            if (n < Ee) g_X[(size_t)m * KP + n] = acc[i][j] + g_q[bq * Ee + n];
        }
    }
}

// ---- K8: predictions = (X @ emb_W^T + w_lin + rowoff) * mask  [TF32 mma] ----
__global__ void __launch_bounds__(256) k8t(const float* __restrict__ embW,
                                           float* __restrict__ out) {
    __shared__ unsigned As[128 * 20];
    __shared__ unsigned Bs[128 * 20];
    int n0 = blockIdx.x * 128;
    int m0 = blockIdx.y * 128;
    int tid = threadIdx.x, lane = tid & 31, wid = tid >> 5;
    int wm = wid >> 2, wn = wid & 3;
    int gid = lane >> 2, ctg = lane & 3;

    float acc[4][4][4];
    #pragma unroll
    for (int mt = 0; mt < 4; mt++)
        #pragma unroll
        for (int nt = 0; nt < 4; nt++)
            #pragma unroll
            for (int r = 0; r < 4; r++) acc[mt][nt][r] = 0.0f;

    for (int kc = 0; kc < KP / 16; kc++) {
        int k0 = kc * 16;
        #pragma unroll
        for (int i = 0; i < 2; i++) {
            int idx = tid + i * 256;
            int row = idx >> 2, seg = (idx & 3) * 4;
            float4 av = *(const float4*)&g_X[(size_t)(m0 + row) * KP + k0 + seg];
            uint4 at;
            at.x = cvt_tf32(av.x); at.y = cvt_tf32(av.y);
            at.z = cvt_tf32(av.z); at.w = cvt_tf32(av.w);
            *(uint4*)&As[row * 20 + seg] = at;
            uint4 bt = make_uint4(0u, 0u, 0u, 0u);
            if (k0 + seg < Ee) {
                float4 bv = *(const float4*)&embW[(size_t)(n0 + row) * Ee + k0 + seg];
                bt.x = cvt_tf32(bv.x); bt.y = cvt_tf32(bv.y);
                bt.z = cvt_tf32(bv.z); bt.w = cvt_tf32(bv.w);
            }
            *(uint4*)&Bs[row * 20 + seg] = bt;
        }
        __syncthreads();
        #pragma unroll
        for (int ka = 0; ka < 16; ka += 8) {
            unsigned afr[4][4], bfr[4][2];
            #pragma unroll
            for (int mt = 0; mt < 4; mt++) {
                int mr = wm * 64 + mt * 16 + gid;
                afr[mt][0] = As[mr * 20 + ka + ctg];
                afr[mt][1] = As[(mr + 8) * 20 + ka + ctg];
                afr[mt][2] = As[mr * 20 + ka + ctg + 4];
                afr[mt][3] = As[(mr + 8) * 20 + ka + ctg + 4];
            }
            #pragma unroll
            for (int nt = 0; nt < 4; nt++) {
                int nr = wn * 32 + nt * 8 + gid;
                bfr[nt][0] = Bs[nr * 20 + ka + ctg];
                bfr[nt][1] = Bs[nr * 20 + ka + ctg + 4];
            }
            #pragma unroll
            for (int mt = 0; mt < 4; mt++)
                #pragma unroll
                for (int nt = 0; nt < 4; nt++)
                    mma_tf32(acc[mt][nt], afr[mt], bfr[nt]);
        }
        __syncthreads();
    }

    #pragma unroll
    for (int mt = 0; mt < 4; mt++) {
        int mA = m0 + wm * 64 + mt * 16 + gid;
        int mB = mA + 8;
        float roA = 0.0f, mkA = 0.0f, roB = 0.0f, mkB = 0.0f;
        if (mA < NROW) { roA = g_rowoff[mA]; mkA = g_maskf[mA]; }
        if (mB < NROW) { roB = g_rowoff[mB]; mkB = g_maskf[mB]; }
        #pragma unroll
        for (int nt = 0; nt < 4; nt++) {
            int v = n0 + wn * 32 + nt * 8 + 2 * ctg;
            float wl0 = g_wlin[v], wl1 = g_wlin[v + 1];
            if (mA < NROW) {
                float2 r;
                r.x = (acc[mt][nt][0] + wl0 + roA) * mkA;
                r.y = (acc[mt][nt][1] + wl1 + roA) * mkA;
                *(float2*)&out[(size_t)mA * Vv + v] = r;
            }
            if (mB < NROW) {
                float2 r;
                r.x = (acc[mt][nt][2] + wl0 + roB) * mkB;
                r.y = (acc[mt][nt][3] + wl1 + roB) * mkB;
                *(float2*)&out[(size_t)mB * Vv + v] = r;
            }
        }
    }
}

// ---------------- launch ----------------
extern "C" void kernel_launch(void* const* d_in, const int* in_sizes, int n_in,
                              void* d_out, int out_size) {
    const float* h0   = (const float*)d_in[0];
    const float* prps = (const float*)d_in[1];
    const int*   caps = (const int*)  d_in[2];
    const int*   clen = (const int*)  d_in[3];
    const float* emb  = (const float*)d_in[4];
    const float* Wih  = (const float*)d_in[5];
    const float* Whh  = (const float*)d_in[6];
    const float* bih  = (const float*)d_in[7];
    const float* bhh  = (const float*)d_in[8];
    const float* whW  = (const float*)d_in[9];
    const float* whb  = (const float*)d_in[10];
    const float* wrW  = (const float*)d_in[11];
    const float* wrb  = (const float*)d_in[12];
    const float* rhW  = (const float*)d_in[13];
    const float* rhb  = (const float*)d_in[14];
    const float* wW   = (const float*)d_in[15];
    const float* wb   = (const float*)d_in[16];
    const float* rW   = (const float*)d_in[17];
    const float* rb   = (const float*)d_in[18];
    float* out = (float*)d_out;

    k0_setup<<<1, 256>>>(clen);
    kw_prep<<<Gg, 256>>>(Wih, Whh, bih, bhh);
    k1_vocab<<<NBLK1, 256>>>(emb, wW, wb);
    k2_derived<<<1, 512>>>(whW, whb, wrW, wrb, wW, wb);
    k3_batch<<<Bb, 1024>>>(h0, prps, caps, emb, wrb, rW, rb, out);
    k3q<<<(Ee + 63) / 64, 256>>>(wrW);
    k4_rh<<<dim3(Hh / 64, (Bb * Pp) / 64), 256>>>(rhW, rhb);
    for (int t = 0; t < TMX; t++) {
        k5t<<<dim3(Gg / 128, 8), 256>>>();
        k6_step<<<Bb, 256>>>(t, caps, emb, whb, out);
    }
    k7_x<<<dim3((Ee + 63) / 64, NROW / 64), 256>>>(whW);
    k8t<<<dim3(Vv / 128, MPAD / 128), 256>>>(emb, out);
}

// round 17
// speedup vs baseline: 1.0036x; 1.0036x over previous
#include <cuda_runtime.h>
#include <cuda_bf16.h>
#include <math.h>

#define Bb    64
#define Tt    20
#define TMX   19
#define Pp    36
#define Vv    32000
#define Ee    300
#define Hh    512
#define Dd    512
#define Gg    2048          // 4*H
#define KL    1324          // E + D + H
#define KPK   1344          // KL padded to 8*168
#define KSPL  168           // per-split K
#define NROW  1216          // B * TMX
#define NBLK1 500           // Vv/64
#define KP    304           // Ee padded to multiple of 16
#define MPAD  1280          // NROW padded to multiple of 128

#define OFF1  ((size_t)Bb*TMX*Vv)
#define OFF2  (OFF1 + (size_t)Bb*TMX*Pp)
#define OFF3  (OFF2 + (size_t)Bb*TMX)
#define OFF4  (OFF3 + (size_t)Bb)

// ---------------- scratch (zero-initialized device globals) ----------------
__device__ int      g_sort[Bb];
__device__ int      g_dec[Bb];
__device__ float    g_epart[NBLK1*Ee];
__device__ float    g_wlin[Vv];
__device__ float    g_sumWH[Hh];
__device__ float    g_sumWRp[Dd];
__device__ float    g_sumwlin;
__device__ float    g_q[Bb*Ee];
__device__ float    g_swrb[Bb];
__device__ float    g_rlin[Bb*Pp];
__device__ float    g_wrsumV[Bb*Pp];
__device__ float    g_props[Bb*Pp*Dd];
__device__ float    g_RH[Bb*Pp*Hh];
__device__ float    g_c[Bb*Hh];
__device__ float    g_Ssum[Bb*Dd];
__device__ float    g_xh[Bb*KPK];       // [emb(300) | fb(512) | h(512) | pad0(20)]
__device__ unsigned g_Whi[Gg*KPK];      // tf32 hi of packed [W_ih | W_hh], pad 0
__device__ unsigned g_Wlo[Gg*KPK];      // tf32 lo
__device__ float    g_bias[Gg];         // b_ih + b_hh
__device__ float    g_gpart[8*Bb*Gg];
__device__ float    g_Hseq[NROW*Hh];
__device__ float    g_X[MPAD*KP];       // padded; pad region stays 0 forever
__device__ float    g_rowoff[NROW];
__device__ float    g_maskf[NROW];

__device__ __forceinline__ float fsig(float x) { return 1.0f / (1.0f + __expf(-x)); }
__device__ __forceinline__ float ftanh(float x) {
    float e = __expf(-2.0f * fabsf(x));
    float r = (1.0f - e) / (1.0f + e);
    return copysignf(r, x);
}
__device__ __forceinline__ float wred(float v) {
    #pragma unroll
    for (int o = 16; o; o >>= 1) v += __shfl_xor_sync(0xffffffffu, v, o);
    return v;
}
__device__ __forceinline__ float wmax(float v) {
    #pragma unroll
    for (int o = 16; o; o >>= 1) v = fmaxf(v, __shfl_xor_sync(0xffffffffu, v, o));
    return v;
}
__device__ __forceinline__ unsigned cvt_tf32(float x) {
    unsigned u;
    asm("cvt.rna.tf32.f32 %0, %1;" : "=r"(u) : "f"(x));
    return u;
}
__device__ __forceinline__ void mma_tf32(float* d, const unsigned* a, const unsigned* b) {
    asm volatile(
        "mma.sync.aligned.m16n8k8.row.col.f32.tf32.tf32.f32 "
        "{%0,%1,%2,%3}, {%4,%5,%6,%7}, {%8,%9}, {%0,%1,%2,%3};"
        : "+f"(d[0]), "+f"(d[1]), "+f"(d[2]), "+f"(d[3])
        : "r"(a[0]), "r"(a[1]), "r"(a[2]), "r"(a[3]), "r"(b[0]), "r"(b[1]));
}

// ---- K0: stable argsort(-lengths) ----
__global__ void k0_setup(const int* __restrict__ clen) {
    __shared__ int len[Bb];
    int t = threadIdx.x;
    if (t < Bb) len[t] = clen[t];
    __syncthreads();
    if (t < Bb) {
        int li = len[t], pos = 0;
        for (int j = 0; j < Bb; j++) {
            int lj = len[j];
            if (lj > li || (lj == li && j < t)) pos++;
        }
        g_sort[pos] = t;
        g_dec[pos]  = li - 1;
    }
}

// ---- KW: pack LSTM weights to tf32 hi/lo, combine biases ----
__global__ void __launch_bounds__(256) kw_prep(const float* __restrict__ Wih,
                                               const float* __restrict__ Whh,
                                               const float* __restrict__ bih,
                                               const float* __restrict__ bhh) {
    int n = blockIdx.x;
    for (int k = threadIdx.x; k < KL; k += 256) {
        float v = (k < Ee + Dd) ? Wih[(size_t)n * (Ee + Dd) + k]
                                : Whh[(size_t)n * Hh + (k - Ee - Dd)];
        unsigned hi = cvt_tf32(v);
        g_Whi[(size_t)n * KPK + k] = hi;
        g_Wlo[(size_t)n * KPK + k] = cvt_tf32(v - __uint_as_float(hi));
    }
    if (threadIdx.x == 0) g_bias[n] = bih[n] + bhh[n];
}

// ---- K1: vocab pass: w_lin + per-block partial column sums of emb_W ----
__global__ void __launch_bounds__(256) k1_vocab(const float* __restrict__ emb,
                                                const float* __restrict__ wW,
                                                const float* __restrict__ wb) {
    __shared__ float swarp[8][Ee];
    int tid = threadIdx.x, lane = tid & 31, w = tid >> 5;
    float wbv = wb[0];
    float seacc[10];
    #pragma unroll
    for (int j = 0; j < 10; j++) seacc[j] = 0.0f;
    #pragma unroll
    for (int r = 0; r < 8; r++) {
        int v = blockIdx.x * 64 + w * 8 + r;
        const float* row = emb + (size_t)v * Ee;
        float acc = 0.0f;
        #pragma unroll
        for (int j = 0; j < 10; j++) {
            int e = lane + 32 * j;
            if (e < Ee) {
                float x = row[e];
                acc += x * wW[e];
                seacc[j] += x;
            }
        }
        acc = wred(acc);
        if (lane == 0) g_wlin[v] = acc + wbv;
    }
    #pragma unroll
    for (int j = 0; j < 10; j++) {
        int e = lane + 32 * j;
        if (e < Ee) swarp[w][e] = seacc[j];
    }
    __syncthreads();
    for (int e = tid; e < Ee; e += 256) {
        float s = 0.0f;
        #pragma unroll
        for (int w2 = 0; w2 < 8; w2++) s += swarp[w2][e];
        g_epart[blockIdx.x * Ee + e] = s;
    }
}

// ---- K2: reduce partials -> sum_emb; derived sums ----
__global__ void k2_derived(const float* __restrict__ whW, const float* __restrict__ whb,
                           const float* __restrict__ wrW, const float* __restrict__ wrb,
                           const float* __restrict__ wW,  const float* __restrict__ wb) {
    __shared__ float se[Ee];
    int t = threadIdx.x;
    for (int e = t; e < Ee; e += 512) {
        float s0 = 0.0f, s1 = 0.0f, s2 = 0.0f, s3 = 0.0f;
        for (int blk = 0; blk < NBLK1; blk += 4) {
            s0 += g_epart[(blk + 0) * Ee + e];
            s1 += g_epart[(blk + 1) * Ee + e];
            s2 += g_epart[(blk + 2) * Ee + e];
            s3 += g_epart[(blk + 3) * Ee + e];
        }
        se[e] = (s0 + s1) + (s2 + s3);
    }
    __syncthreads();
    if (t < Hh) {
        const float* r1 = whW + t * Ee;
        const float* r2 = wrW + t * Ee;
        float a = 0.0f, b2 = 0.0f;
        for (int e = 0; e < Ee; e++) { a += r1[e] * se[e]; b2 += r2[e] * se[e]; }
        g_sumWH[t]  = a  + (float)Vv * whb[t];
        g_sumWRp[t] = b2 + (float)Vv * wrb[t];
    }
    if (t == 0) {
        float s = 0.0f;
        for (int e = 0; e < Ee; e++) s += wW[e] * se[e];
        g_sumwlin = s + (float)Vv * wb[0];
    }
}

// ---- K3: per-batch setup ----
__global__ void __launch_bounds__(1024) k3_batch(
        const float* __restrict__ h0, const float* __restrict__ props,
        const int* __restrict__ caps, const float* __restrict__ emb,
        const float* __restrict__ wrb,
        const float* __restrict__ rW,  const float* __restrict__ rb,
        float* __restrict__ out) {
    int b = blockIdx.x, tid = threadIdx.x, lane = tid & 31, w = tid >> 5;
    int sb = g_sort[b];
    const float* pb = props + (size_t)sb * Pp * Dd;
    float* gp = g_props + (size_t)b * Pp * Dd;
    __shared__ float sS[Dd];

    for (int i = tid; i < Pp * Dd / 4; i += 1024)
        ((float4*)gp)[i] = ((const float4*)pb)[i];
    if (tid < Dd) {
        float s = 0.0f;
        #pragma unroll
        for (int p = 0; p < Pp; p++) s += pb[p * Dd + tid];
        sS[tid] = s;
        g_Ssum[b * Dd + tid] = s;
    }
    __syncthreads();

    if (w == 0) {
        float a = 0.0f;
        for (int d = lane; d < Dd; d += 32) a += sS[d] * wrb[d];
        a = wred(a);
        if (lane == 0) g_swrb[b] = a;
    }
    for (int p = w; p < Pp; p += 32) {
        float a1 = 0.0f, a2 = 0.0f;
        const float* rowp = pb + p * Dd;
        for (int d = lane; d < Dd; d += 32) {
            float x = rowp[d];
            a1 += x * rW[d];
            a2 += x * g_sumWRp[d];
        }
        a1 = wred(a1); a2 = wred(a2);
        if (lane == 0) {
            g_rlin[b * Pp + p]   = a1 + rb[0];
            g_wrsumV[b * Pp + p] = a2;
        }
    }
    if (tid < Hh) {
        float v = h0[(size_t)sb * Hh + tid];
        g_c[b * Hh + tid] = v;
        g_xh[b * KPK + Ee + Dd + tid] = v;   // h
        g_xh[b * KPK + Ee + tid] = 0.0f;     // fb
    }
    int cap0 = caps[sb * Tt + 0];
    if (tid < Ee) g_xh[b * KPK + tid] = emb[(size_t)cap0 * Ee + tid];
    int dec = g_dec[b];
    if (tid < TMX) {
        g_maskf[b * TMX + tid] = (tid < dec) ? 1.0f : 0.0f;
        out[OFF2 + b * TMX + tid] = (float)caps[sb * Tt + 1 + tid];
    }
    if (tid == 0) {
        out[OFF3 + b] = (float)dec;
        out[OFF4 + b] = (float)sb;
    }
}

// ---- K3Q: q = Ssum(64x512) @ wr_W(512x300) ----
__global__ void __launch_bounds__(256) k3q(const float* __restrict__ wrW) {
    __shared__ float As[16][64];
    __shared__ float Bs[16][64];
    int n0 = blockIdx.x * 64;
    int tid = threadIdx.x, tx = tid & 15, ty = tid >> 4;
    float acc[4][4] = {};
    for (int k0 = 0; k0 < Dd; k0 += 16) {
        #pragma unroll
        for (int i = 0; i < 4; i++) {
            int idx = tid + i * 256;
            int kk = idx & 15, mm = idx >> 4;
            As[kk][mm] = g_Ssum[mm * Dd + k0 + kk];
            int nn = idx & 63, kk2 = idx >> 6;
            Bs[kk2][nn] = (n0 + nn < Ee) ? wrW[(size_t)(k0 + kk2) * Ee + n0 + nn] : 0.0f;
        }
        __syncthreads();
        #pragma unroll
        for (int kk = 0; kk < 16; kk++) {
            float4 a  = *(const float4*)&As[kk][ty * 4];
            float4 bq = *(const float4*)&Bs[kk][tx * 4];
            float av[4] = {a.x, a.y, a.z, a.w};
            float bv[4] = {bq.x, bq.y, bq.z, bq.w};
            #pragma unroll
            for (int i = 0; i < 4; i++)
                #pragma unroll
                for (int j = 0; j < 4; j++) acc[i][j] += av[i] * bv[j];
        }
        __syncthreads();
    }
    #pragma unroll
    for (int i = 0; i < 4; i++)
        #pragma unroll
        for (int j = 0; j < 4; j++) {
            int n = n0 + tx * 4 + j;
            if (n < Ee) g_q[(ty * 4 + i) * Ee + n] = acc[i][j];
        }
}

// ---- K4: RH = props_s @ rh_W^T + rh_b ----
__global__ void __launch_bounds__(256) k4_rh(const float* __restrict__ rhW,
                                             const float* __restrict__ rhb) {
    __shared__ float As[16][64];
    __shared__ float Bs[16][64];
    int m0 = blockIdx.y * 64, n0 = blockIdx.x * 64;
    int tid = threadIdx.x, tx = tid & 15, ty = tid >> 4;
    float acc[4][4] = {};
    for (int k0 = 0; k0 < Dd; k0 += 16) {
        #pragma unroll
        for (int i = 0; i < 4; i++) {
            int idx = tid + i * 256;
            int kk = idx & 15, mm = idx >> 4;
            As[kk][mm] = g_props[(size_t)(m0 + mm) * Dd + k0 + kk];
            Bs[kk][mm] = rhW[(size_t)(n0 + mm) * Dd + k0 + kk];
        }
        __syncthreads();
        #pragma unroll
        for (int kk = 0; kk < 16; kk++) {
            float4 a  = *(const float4*)&As[kk][ty * 4];
            float4 bq = *(const float4*)&Bs[kk][tx * 4];
            float av[4] = {a.x, a.y, a.z, a.w};
            float bv[4] = {bq.x, bq.y, bq.z, bq.w};
            #pragma unroll
            for (int i = 0; i < 4; i++)
                #pragma unroll
                for (int j = 0; j < 4; j++) acc[i][j] += av[i] * bv[j];
        }
        __syncthreads();
    }
    #pragma unroll
    for (int i = 0; i < 4; i++)
        #pragma unroll
        for (int j = 0; j < 4; j++)
            g_RH[(size_t)(m0 + ty * 4 + i) * Hh + n0 + tx * 4 + j] = acc[i][j] + rhb[n0 + tx * 4 + j];
}

// ---- K5T: gates split-K via 2-term TF32 mma (fp32-accurate) ----
__global__ void __launch_bounds__(256) k5t() {
    __shared__ unsigned Ah[64 * 12], Al[64 * 12];
    __shared__ unsigned Bh[128 * 12], Bl[128 * 12];
    int n0 = blockIdx.x * 128;
    int ks = blockIdx.y * KSPL;
    int tid = threadIdx.x, lane = tid & 31, wid = tid >> 5;
    int wm = wid >> 2, wn = wid & 3;
    int gid = lane >> 2, ctg = lane & 3;

    float acc[2][4][4];
    #pragma unroll
    for (int mt = 0; mt < 2; mt++)
        #pragma unroll
        for (int nt = 0; nt < 4; nt++)
            #pragma unroll
            for (int r = 0; r < 4; r++) acc[mt][nt][r] = 0.0f;

    int brow = tid >> 1, bseg = (tid & 1) * 4;
    #pragma unroll 1
    for (int c = 0; c < KSPL / 8; c++) {
        int k0 = ks + c * 8;
        *(uint4*)&Bh[brow * 12 + bseg] = *(const uint4*)&g_Whi[(size_t)(n0 + brow) * KPK + k0 + bseg];
        *(uint4*)&Bl[brow * 12 + bseg] = *(const uint4*)&g_Wlo[(size_t)(n0 + brow) * KPK + k0 + bseg];
        if (tid < 128) {
            float4 av = *(const float4*)&g_xh[brow * KPK + k0 + bseg];
            uint4 h, l;
            h.x = cvt_tf32(av.x); l.x = cvt_tf32(av.x - __uint_as_float(h.x));
            h.y = cvt_tf32(av.y); l.y = cvt_tf32(av.y - __uint_as_float(h.y));
            h.z = cvt_tf32(av.z); l.z = cvt_tf32(av.z - __uint_as_float(h.z));
            h.w = cvt_tf32(av.w); l.w = cvt_tf32(av.w - __uint_as_float(h.w));
            *(uint4*)&Ah[brow * 12 + bseg] = h;
            *(uint4*)&Al[brow * 12 + bseg] = l;
        }
        __syncthreads();
        unsigned ah[2][4], al[2][4], bh[4][2], bl[4][2];
        #pragma unroll
        for (int mt = 0; mt < 2; mt++) {
            int mr = wm * 32 + mt * 16 + gid;
            ah[mt][0] = Ah[mr * 12 + ctg];       al[mt][0] = Al[mr * 12 + ctg];
            ah[mt][1] = Ah[(mr + 8) * 12 + ctg]; al[mt][1] = Al[(mr + 8) * 12 + ctg];
            ah[mt][2] = Ah[mr * 12 + ctg + 4];   al[mt][2] = Al[mr * 12 + ctg + 4];
            ah[mt][3] = Ah[(mr + 8) * 12 + ctg + 4]; al[mt][3] = Al[(mr + 8) * 12 + ctg + 4];
        }
        #pragma unroll
        for (int nt = 0; nt < 4; nt++) {
            int nr = wn * 32 + nt * 8 + gid;
            bh[nt][0] = Bh[nr * 12 + ctg];     bl[nt][0] = Bl[nr * 12 + ctg];
            bh[nt][1] = Bh[nr * 12 + ctg + 4]; bl[nt][1] = Bl[nr * 12 + ctg + 4];
        }
        #pragma unroll
        for (int mt = 0; mt < 2; mt++)
            #pragma unroll
            for (int nt = 0; nt < 4; nt++) {
                mma_tf32(acc[mt][nt], ah[mt], bh[nt]);
                mma_tf32(acc[mt][nt], ah[mt], bl[nt]);
                mma_tf32(acc[mt][nt], al[mt], bh[nt]);
            }
        __syncthreads();
    }
    float* pp = g_gpart + (size_t)blockIdx.y * Bb * Gg;
    #pragma unroll
    for (int mt = 0; mt < 2; mt++) {
        int mA = wm * 32 + mt * 16 + gid;
        int mB = mA + 8;
        #pragma unroll
        for (int nt = 0; nt < 4; nt++) {
            int v = n0 + wn * 32 + nt * 8 + 2 * ctg;
            *(float2*)&pp[mA * Gg + v] = make_float2(acc[mt][nt][0], acc[mt][nt][1]);
            *(float2*)&pp[mB * Gg + v] = make_float2(acc[mt][nt][2], acc[mt][nt][3]);
        }
    }
}

// ---- K6: per-step: LSTM pointwise + attention + state update ----
__global__ void __launch_bounds__(256) k6_step(int t, const int* __restrict__ caps,
                                               const float* __restrict__ emb,
                                               const float* __restrict__ whb,
                                               float* __restrict__ out) {
    int b = blockIdx.x, tid = threadIdx.x, lane = tid & 31, w = tid >> 5;
    __shared__ float sh[Hh], sr[Pp], satt[Pp], sred[16];
    __shared__ float s_hdot, s_hwb;

    float mask = g_maskf[b * TMX + t];
    float hdot_part = 0.0f, hwb_part = 0.0f;
    #pragma unroll
    for (int u = 0; u < 2; u++) {
        int h = tid + u * 256;
        float gi = g_bias[h];
        float gf = g_bias[512 + h];
        float gg = g_bias[1024 + h];
        float go = g_bias[1536 + h];
        #pragma unroll
        for (int s = 0; s < 8; s++) {
            const float* pp = g_gpart + (size_t)s * Bb * Gg + (size_t)b * Gg;
            gi += pp[h]; gf += pp[512 + h]; gg += pp[1024 + h]; go += pp[1536 + h];
        }
        float co = g_c[b * Hh + h];
        float cn = fsig(gf) * co + fsig(gi) * ftanh(gg);
        float hn = fsig(go) * ftanh(cn);
        sh[h] = hn;
        g_Hseq[(size_t)(b * TMX + t) * Hh + h] = hn;
        float hold = g_xh[b * KPK + Ee + Dd + h];
        g_c[b * Hh + h] = mask * cn + (1.0f - mask) * co;
        g_xh[b * KPK + Ee + Dd + h] = mask * hn + (1.0f - mask) * hold;
        hdot_part += hn * g_sumWH[h];
        hwb_part  += hn * whb[h];
    }
    hdot_part = wred(hdot_part);
    hwb_part  = wred(hwb_part);
    if (lane == 0) { sred[w] = hdot_part; sred[8 + w] = hwb_part; }
    __syncthreads();
    if (tid == 0) {
        float a = 0.0f, b2 = 0.0f;
        #pragma unroll
        for (int i = 0; i < 8; i++) { a += sred[i]; b2 += sred[8 + i]; }
        s_hdot = a; s_hwb = b2;
    }
    __syncthreads();

    for (int p = w; p < Pp; p += 8) {
        const float* rh = g_RH + (size_t)(b * Pp + p) * Hh;
        float a = 0.0f;
        for (int d = lane; d < Hh; d += 32) a += rh[d] * sh[d];
        a = wred(a);
        if (lane == 0) sr[p] = a + g_rlin[b * Pp + p];
    }
    __syncthreads();

    // warp 0: parallel softmax over 36 logits + rowoff
    if (w == 0) {
        float base = s_hdot + g_sumwlin;
        float r0v = (lane < Pp) ? sr[lane] : 0.0f;
        float r1v = (lane + 32 < Pp) ? sr[lane + 32] : 0.0f;
        float l0 = (lane < Pp) ? (base + g_wrsumV[b * Pp + lane] + r0v) : -1e30f;
        float l1 = (lane + 32 < Pp) ? (base + g_wrsumV[b * Pp + lane + 32] + r1v) : -1e30f;
        float mx = wmax(fmaxf(l0, l1));
        float e0 = (lane < Pp) ? __expf(l0 - mx) : 0.0f;
        float e1 = (lane + 32 < Pp) ? __expf(l1 - mx) : 0.0f;
        float den = wred(e0 + e1);
        float inv = 1.0f / den;
        if (lane < Pp) satt[lane] = e0 * inv;
        if (lane + 32 < Pp) satt[lane + 32] = e1 * inv;
        float rs = wred(r0v + r1v);
        if (lane == 0) g_rowoff[b * TMX + t] = rs + s_hwb + g_swrb[b];
    }
    __syncthreads();
    if (tid < Pp) out[OFF1 + (size_t)(b * TMX + t) * Pp + tid] = satt[tid] * mask;

    int capn = (t < TMX - 1) ? caps[g_sort[b] * Tt + t + 1] : 0;
    #pragma unroll
    for (int u = 0; u < 2; u++) {
        int d = tid + u * 256;
        float fbn = 0.0f;
        #pragma unroll 4
        for (int p = 0; p < Pp; p++) fbn += satt[p] * g_props[(size_t)(b * Pp + p) * Dd + d];
        float fold = g_xh[b * KPK + Ee + d];
        g_xh[b * KPK + Ee + d] = mask * fbn + (1.0f - mask) * fold;
    }
    // FIX: strided loop — Ee=300 > blockDim=256, the guard version left 44
    // stale embedding components per step (the 4.2e-2 failure).
    if (t < TMX - 1)
        for (int e = tid; e < Ee; e += 256)
            g_xh[b * KPK + e] = emb[(size_t)capn * Ee + e];
}

// ---- K7: X = Hseq @ wh_W + q  (writes into KP-padded g_X) ----
__global__ void __launch_bounds__(256) k7_x(const float* __restrict__ whW) {
    __shared__ float As[16][64];
    __shared__ float Bs[16][64];
    int m0 = blockIdx.y * 64, n0 = blockIdx.x * 64;
    int tid = threadIdx.x, tx = tid & 15, ty = tid >> 4;
    float acc[4][4] = {};
    for (int k0 = 0; k0 < Hh; k0 += 16) {
        #pragma unroll
        for (int i = 0; i < 4; i++) {
            int idxa = tid + i * 256;
            int kk = idxa & 15, mm = idxa >> 4;
            As[kk][mm] = g_Hseq[(size_t)(m0 + mm) * Hh + k0 + kk];
            int nn = idxa & 63, kk2 = idxa >> 6;
            Bs[kk2][nn] = (n0 + nn < Ee) ? whW[(size_t)(k0 + kk2) * Ee + n0 + nn] : 0.0f;
        }
        __syncthreads();
        #pragma unroll
        for (int kk = 0; kk < 16; kk++) {
            float4 a  = *(const float4*)&As[kk][ty * 4];
            float4 bq = *(const float4*)&Bs[kk][tx * 4];
            float av[4] = {a.x, a.y, a.z, a.w};
            float bv[4] = {bq.x, bq.y, bq.z, bq.w};
            #pragma unroll
            for (int i = 0; i < 4; i++)
                #pragma unroll
                for (int j = 0; j < 4; j++) acc[i][j] += av[i] * bv[j];
        }
        __syncthreads();
    }
    #pragma unroll
    for (int i = 0; i < 4; i++) {
        int m = m0 + ty * 4 + i;
        int bq = m / TMX;
        #pragma unroll
        for (int j = 0; j < 4; j++) {
            int n = n0 + tx * 4 + j;
            if (n < Ee) g_X[(size_t)m * KP + n] = acc[i][j] + g_q[bq * Ee + n];
        }
    }
}

// ---- K8: predictions = (X @ emb_W^T + w_lin + rowoff) * mask  [TF32 mma] ----
__global__ void __launch_bounds__(256) k8t(const float* __restrict__ embW,
                                           float* __restrict__ out) {
    __shared__ unsigned As[128 * 20];
    __shared__ unsigned Bs[128 * 20];
    int n0 = blockIdx.x * 128;
    int m0 = blockIdx.y * 128;
    int tid = threadIdx.x, lane = tid & 31, wid = tid >> 5;
    int wm = wid >> 2, wn = wid & 3;
    int gid = lane >> 2, ctg = lane & 3;

    float acc[4][4][4];
    #pragma unroll
    for (int mt = 0; mt < 4; mt++)
        #pragma unroll
        for (int nt = 0; nt < 4; nt++)
            #pragma unroll
            for (int r = 0; r < 4; r++) acc[mt][nt][r] = 0.0f;

    for (int kc = 0; kc < KP / 16; kc++) {
        int k0 = kc * 16;
        #pragma unroll
        for (int i = 0; i < 2; i++) {
            int idx = tid + i * 256;
            int row = idx >> 2, seg = (idx & 3) * 4;
            float4 av = *(const float4*)&g_X[(size_t)(m0 + row) * KP + k0 + seg];
            uint4 at;
            at.x = cvt_tf32(av.x); at.y = cvt_tf32(av.y);
            at.z = cvt_tf32(av.z); at.w = cvt_tf32(av.w);
            *(uint4*)&As[row * 20 + seg] = at;
            uint4 bt = make_uint4(0u, 0u, 0u, 0u);
            if (k0 + seg < Ee) {
                float4 bv = *(const float4*)&embW[(size_t)(n0 + row) * Ee + k0 + seg];
                bt.x = cvt_tf32(bv.x); bt.y = cvt_tf32(bv.y);
                bt.z = cvt_tf32(bv.z); bt.w = cvt_tf32(bv.w);
            }
            *(uint4*)&Bs[row * 20 + seg] = bt;
        }
        __syncthreads();
        #pragma unroll
        for (int ka = 0; ka < 16; ka += 8) {
            unsigned afr[4][4], bfr[4][2];
            #pragma unroll
            for (int mt = 0; mt < 4; mt++) {
                int mr = wm * 64 + mt * 16 + gid;
                afr[mt][0] = As[mr * 20 + ka + ctg];
                afr[mt][1] = As[(mr + 8) * 20 + ka + ctg];
                afr[mt][2] = As[mr * 20 + ka + ctg + 4];
                afr[mt][3] = As[(mr + 8) * 20 + ka + ctg + 4];
            }
            #pragma unroll
            for (int nt = 0; nt < 4; nt++) {
                int nr = wn * 32 + nt * 8 + gid;
                bfr[nt][0] = Bs[nr * 20 + ka + ctg];
                bfr[nt][1] = Bs[nr * 20 + ka + ctg + 4];
            }
            #pragma unroll
            for (int mt = 0; mt < 4; mt++)
                #pragma unroll
                for (int nt = 0; nt < 4; nt++)
                    mma_tf32(acc[mt][nt], afr[mt], bfr[nt]);
        }
        __syncthreads();
    }

    #pragma unroll
    for (int mt = 0; mt < 4; mt++) {
        int mA = m0 + wm * 64 + mt * 16 + gid;
        int mB = mA + 8;
        float roA = 0.0f, mkA = 0.0f, roB = 0.0f, mkB = 0.0f;
        if (mA < NROW) { roA = g_rowoff[mA]; mkA = g_maskf[mA]; }
        if (mB < NROW) { roB = g_rowoff[mB]; mkB = g_maskf[mB]; }
        #pragma unroll
        for (int nt = 0; nt < 4; nt++) {
            int v = n0 + wn * 32 + nt * 8 + 2 * ctg;
            float wl0 = g_wlin[v], wl1 = g_wlin[v + 1];
            if (mA < NROW) {
                float2 r;
                r.x = (acc[mt][nt][0] + wl0 + roA) * mkA;
                r.y = (acc[mt][nt][1] + wl1 + roA) * mkA;
                *(float2*)&out[(size_t)mA * Vv + v] = r;
            }
            if (mB < NROW) {
                float2 r;
                r.x = (acc[mt][nt][2] + wl0 + roB) * mkB;
                r.y = (acc[mt][nt][3] + wl1 + roB) * mkB;
                *(float2*)&out[(size_t)mB * Vv + v] = r;
            }
        }
    }
}

// ---------------- launch ----------------
extern "C" void kernel_launch(void* const* d_in, const int* in_sizes, int n_in,
                              void* d_out, int out_size) {
    const float* h0   = (const float*)d_in[0];
    const float* prps = (const float*)d_in[1];
    const int*   caps = (const int*)  d_in[2];
    const int*   clen = (const int*)  d_in[3];
    const float* emb  = (const float*)d_in[4];
    const float* Wih  = (const float*)d_in[5];
    const float* Whh  = (const float*)d_in[6];
    const float* bih  = (const float*)d_in[7];
    const float* bhh  = (const float*)d_in[8];
    const float* whW  = (const float*)d_in[9];
    const float* whb  = (const float*)d_in[10];
    const float* wrW  = (const float*)d_in[11];
    const float* wrb  = (const float*)d_in[12];
    const float* rhW  = (const float*)d_in[13];
    const float* rhb  = (const float*)d_in[14];
    const float* wW   = (const float*)d_in[15];
    const float* wb   = (const float*)d_in[16];
    const float* rW   = (const float*)d_in[17];
    const float* rb   = (const float*)d_in[18];
    float* out = (float*)d_out;

    k0_setup<<<1, 256>>>(clen);
    kw_prep<<<Gg, 256>>>(Wih, Whh, bih, bhh);
    k1_vocab<<<NBLK1, 256>>>(emb, wW, wb);
    k2_derived<<<1, 512>>>(whW, whb, wrW, wrb, wW, wb);
    k3_batch<<<Bb, 1024>>>(h0, prps, caps, emb, wrb, rW, rb, out);
    k3q<<<(Ee + 63) / 64, 256>>>(wrW);
    k4_rh<<<dim3(Hh / 64, (Bb * Pp) / 64), 256>>>(rhW, rhb);
    for (int t = 0; t < TMX; t++) {
        k5t<<<dim3(Gg / 128, 8), 256>>>();
        k6_step<<<Bb, 256>>>(t, caps, emb, whb, out);
    }
    k7_x<<<dim3((Ee + 63) / 64, NROW / 64), 256>>>(whW);
    k8t<<<dim3(Vv / 128, MPAD / 128), 256>>>(emb, out);
}